// round 1
// baseline (speedup 1.0000x reference)
#include <cuda_runtime.h>
#include <cuda_bf16.h>

#define N_TOK 16384
#define D_IN  512
#define D_OUT 512
#define NE    16

#define BM 128
#define BN 128
#define BK 16

// Scratch (no allocations allowed): per-expert token lists
__device__ int   g_count[NE];
__device__ int   g_tok[NE * N_TOK];
__device__ float g_wt [NE * N_TOK];

// ---------------------------------------------------------------------------
// Router: logits -> top2 -> softmax -> scatter into per-expert lists
// block = 256 threads = 16 tokens x 16 experts
// ---------------------------------------------------------------------------
__global__ __launch_bounds__(256) void router_kernel(
    const float* __restrict__ x,
    const float* __restrict__ gw,   // [D_IN, NE]
    const float* __restrict__ gb)   // [NE]
{
    __shared__ float s_gw[D_IN * NE];          // 32 KB
    __shared__ float s_log[16][NE];

    int tid = threadIdx.x;
    for (int i = tid; i < D_IN * NE; i += 256) s_gw[i] = gw[i];
    __syncthreads();

    int e  = tid & 15;
    int tl = tid >> 4;
    int t  = blockIdx.x * 16 + tl;

    const float* xr = x + (size_t)t * D_IN;
    float acc = gb[e];
    #pragma unroll 8
    for (int d = 0; d < D_IN; d++)
        acc = fmaf(xr[d], s_gw[d * NE + e], acc);
    s_log[tl][e] = acc;
    __syncthreads();

    if (e == 0) {
        // top-1 (ties -> lowest index, matching jax top_k)
        float b1 = -1e30f; int i1 = 0;
        #pragma unroll
        for (int j = 0; j < NE; j++) {
            float v = s_log[tl][j];
            if (v > b1) { b1 = v; i1 = j; }
        }
        float b2 = -1e30f; int i2 = 0;
        #pragma unroll
        for (int j = 0; j < NE; j++) {
            if (j == i1) continue;
            float v = s_log[tl][j];
            if (v > b2) { b2 = v; i2 = j; }
        }
        // softmax over (b1, b2), b1 is max
        float z  = expf(b2 - b1);
        float s  = 1.0f + z;
        float w1 = 1.0f / s;
        float w2 = z / s;

        int p = atomicAdd(&g_count[i1], 1);
        g_tok[i1 * N_TOK + p] = t;  g_wt[i1 * N_TOK + p] = w1;
        p = atomicAdd(&g_count[i2], 1);
        g_tok[i2 * N_TOK + p] = t;  g_wt[i2 * N_TOK + p] = w2;
    }
}

// ---------------------------------------------------------------------------
// Grouped GEMM per expert over gathered token lists.
// grid = (D_OUT/BN, N_TOK/BM, NE), block = 256 threads, 8x8 per-thread tile.
// out[t] += w * (x[t] @ W[e] + b[e])  via atomicAdd (exactly 2 adds/element).
// ---------------------------------------------------------------------------
__global__ __launch_bounds__(256) void moe_gemm_kernel(
    const float* __restrict__ x,
    const float* __restrict__ ew,   // [NE, D_IN, D_OUT]
    const float* __restrict__ eb,   // [NE, D_OUT]
    float* __restrict__ out)        // [N_TOK, D_OUT]
{
    int e   = blockIdx.z;
    int cnt = g_count[e];
    int m0  = blockIdx.y * BM;
    if (m0 >= cnt) return;
    int n0  = blockIdx.x * BN;

    __shared__ __align__(16) float As[BK][BM];
    __shared__ __align__(16) float Bs[BK][BN];
    __shared__ int   s_tok[BM];
    __shared__ float s_w[BM];

    int tid = threadIdx.x;

    if (tid < BM) {
        int gm = m0 + tid;
        if (gm < cnt) {
            s_tok[tid] = g_tok[e * N_TOK + gm];
            s_w[tid]   = g_wt [e * N_TOK + gm];
        } else {
            s_tok[tid] = -1;
            s_w[tid]   = 0.0f;
        }
    }
    __syncthreads();

    // A-loader mapping: quad q covers k = q*4..q*4+3, row = tid>>2 (+64)
    int a_q = (tid & 3) * 4;
    int a_r = tid >> 2;
    // B-loader mapping: 32 float4 per row, rows tid>>5 and +8
    int b_c = (tid & 31) * 4;
    int b_r = tid >> 5;

    const float* wbase = ew + (size_t)e * D_IN * D_OUT;

    int trow = (tid >> 4) << 3;   // 0..120
    int tcol = (tid & 15) << 3;   // 0..120

    float acc[8][8];
    #pragma unroll
    for (int i = 0; i < 8; i++)
        #pragma unroll
        for (int j = 0; j < 8; j++) acc[i][j] = 0.0f;

    for (int k0 = 0; k0 < D_IN; k0 += BK) {
        // load A (gathered token rows), transposed into As[k][m]
        #pragma unroll
        for (int h = 0; h < 2; h++) {
            int row = a_r + h * 64;
            int tk  = s_tok[row];
            float4 v = make_float4(0.f, 0.f, 0.f, 0.f);
            if (tk >= 0)
                v = *(const float4*)(x + (size_t)tk * D_IN + k0 + a_q);
            As[a_q + 0][row] = v.x;
            As[a_q + 1][row] = v.y;
            As[a_q + 2][row] = v.z;
            As[a_q + 3][row] = v.w;
        }
        // load B
        #pragma unroll
        for (int h = 0; h < 2; h++) {
            int row = b_r + h * 8;
            float4 v = *(const float4*)(wbase + (size_t)(k0 + row) * D_OUT + n0 + b_c);
            *(float4*)&Bs[row][b_c] = v;
        }
        __syncthreads();

        #pragma unroll
        for (int kk = 0; kk < BK; kk++) {
            float a[8], b[8];
            *(float4*)&a[0] = *(const float4*)&As[kk][trow];
            *(float4*)&a[4] = *(const float4*)&As[kk][trow + 4];
            *(float4*)&b[0] = *(const float4*)&Bs[kk][tcol];
            *(float4*)&b[4] = *(const float4*)&Bs[kk][tcol + 4];
            #pragma unroll
            for (int i = 0; i < 8; i++)
                #pragma unroll
                for (int j = 0; j < 8; j++)
                    acc[i][j] = fmaf(a[i], b[j], acc[i][j]);
        }
        __syncthreads();
    }

    // epilogue: out[t][n] += w * (acc + bias)
    float bi[8];
    const float* bias = eb + (size_t)e * D_OUT + n0;
    #pragma unroll
    for (int j = 0; j < 8; j++) bi[j] = bias[tcol + j];

    #pragma unroll
    for (int i = 0; i < 8; i++) {
        int row = trow + i;
        int tk  = s_tok[row];
        if (tk < 0) continue;
        float w = s_w[row];
        float* orow = out + (size_t)tk * D_OUT + n0;
        #pragma unroll
        for (int j = 0; j < 8; j++)
            atomicAdd(&orow[tcol + j], w * (acc[i][j] + bi[j]));
    }
}

// ---------------------------------------------------------------------------
extern "C" void kernel_launch(void* const* d_in, const int* in_sizes, int n_in,
                              void* d_out, int out_size)
{
    const float* x  = (const float*)d_in[0];
    const float* gw = (const float*)d_in[1];
    const float* gb = (const float*)d_in[2];
    const float* ew = (const float*)d_in[3];
    const float* eb = (const float*)d_in[4];
    float* out = (float*)d_out;

    void* cptr = nullptr;
    cudaGetSymbolAddress(&cptr, g_count);
    cudaMemsetAsync(cptr, 0, NE * sizeof(int));
    cudaMemsetAsync(d_out, 0, (size_t)out_size * sizeof(float));

    router_kernel<<<N_TOK / 16, 256>>>(x, gw, gb);

    dim3 grid(D_OUT / BN, N_TOK / BM, NE);
    moe_gemm_kernel<<<grid, 256>>>(x, ew, eb, out);
}

// round 5
// speedup vs baseline: 1.7723x; 1.7723x over previous
#include <cuda_runtime.h>
#include <cuda_bf16.h>
#include <cstdint>

#define N_TOK 16384
#define D_IN  512
#define D_OUT 512
#define NE    16

#define BM 128
#define BN 128
#define BKC 64
#define SMEM_DYN (4*16384 + 1024)

// ---------------- scratch (no allocations allowed) ----------------
__device__ int   g_count[NE];
__device__ int   g_base[NE];
__device__ int   g_tok[NE * N_TOK];
__device__ float g_wt [NE * N_TOK];
__device__ int4  g_assign[N_TOK];                 // (e1,p1,e2,p2) per token
__device__ float g_scratch[2 * N_TOK * D_OUT];    // 64 MB per-assignment outputs

// ---------------- helpers ----------------
__device__ __forceinline__ uint32_t smem_u32(const void* p) {
    uint32_t a;
    asm("{ .reg .u64 t; cvta.to.shared.u64 t, %1; cvt.u32.u64 %0, t; }" : "=r"(a) : "l"(p));
    return a;
}

__device__ __forceinline__ uint32_t swz(uint32_t off) {      // SW128
    return off ^ ((off >> 3) & 0x70);
}

__device__ __forceinline__ void ldsm_x4(uint32_t* r, uint32_t addr) {
    asm volatile("ldmatrix.sync.aligned.m8n8.x4.shared.b16 {%0,%1,%2,%3}, [%4];"
        : "=r"(r[0]), "=r"(r[1]), "=r"(r[2]), "=r"(r[3]) : "r"(addr));
}
__device__ __forceinline__ void ldsm_x4t(uint32_t* r, uint32_t addr) {
    asm volatile("ldmatrix.sync.aligned.m8n8.x4.trans.shared.b16 {%0,%1,%2,%3}, [%4];"
        : "=r"(r[0]), "=r"(r[1]), "=r"(r[2]), "=r"(r[3]) : "r"(addr));
}

__device__ __forceinline__ void mma_bf16(float* c, const uint32_t* a, const uint32_t* b) {
    asm volatile("mma.sync.aligned.m16n8k16.row.col.f32.bf16.bf16.f32 "
        "{%0,%1,%2,%3}, {%4,%5,%6,%7}, {%8,%9}, {%0,%1,%2,%3};"
        : "+f"(c[0]), "+f"(c[1]), "+f"(c[2]), "+f"(c[3])
        : "r"(a[0]), "r"(a[1]), "r"(a[2]), "r"(a[3]), "r"(b[0]), "r"(b[1]));
}

__device__ __forceinline__ uint32_t pack_bf2(float a, float b) {
    __nv_bfloat162 t = __floats2bfloat162_rn(a, b);
    return *reinterpret_cast<uint32_t*>(&t);
}

// float4 -> (hi, lo=residual) bf16x4, stored 8B each at SW128-swizzled offset
__device__ __forceinline__ void store_hl(char* ph, char* pl, uint32_t off, float4 v) {
    uint32_t so = swz(off);
    __nv_bfloat16 h0 = __float2bfloat16_rn(v.x);
    __nv_bfloat16 h1 = __float2bfloat16_rn(v.y);
    __nv_bfloat16 h2 = __float2bfloat16_rn(v.z);
    __nv_bfloat16 h3 = __float2bfloat16_rn(v.w);
    float l0 = v.x - __bfloat162float(h0);
    float l1 = v.y - __bfloat162float(h1);
    float l2 = v.z - __bfloat162float(h2);
    float l3 = v.w - __bfloat162float(h3);
    *reinterpret_cast<uint2*>(ph + so) = make_uint2(pack_bf2(v.x, v.y), pack_bf2(v.z, v.w));
    *reinterpret_cast<uint2*>(pl + so) = make_uint2(pack_bf2(l0, l1),  pack_bf2(l2, l3));
}

// ---------------------------------------------------------------------------
// Router
// ---------------------------------------------------------------------------
__global__ __launch_bounds__(256) void router_kernel(
    const float* __restrict__ x,
    const float* __restrict__ gw,
    const float* __restrict__ gb)
{
    __shared__ float s_gw[D_IN * NE];
    __shared__ float s_log[16][NE];

    int tid = threadIdx.x;
    for (int i = tid; i < D_IN * NE; i += 256) s_gw[i] = gw[i];
    __syncthreads();

    int e  = tid & 15;
    int tl = tid >> 4;
    int t  = blockIdx.x * 16 + tl;

    const float* xr = x + (size_t)t * D_IN;
    float acc = gb[e];
    #pragma unroll 8
    for (int d = 0; d < D_IN; d++)
        acc = fmaf(xr[d], s_gw[d * NE + e], acc);
    s_log[tl][e] = acc;
    __syncthreads();

    if (e == 0) {
        float b1 = -1e30f; int i1 = 0;
        #pragma unroll
        for (int j = 0; j < NE; j++) {
            float v = s_log[tl][j];
            if (v > b1) { b1 = v; i1 = j; }
        }
        float b2 = -1e30f; int i2 = 0;
        #pragma unroll
        for (int j = 0; j < NE; j++) {
            if (j == i1) continue;
            float v = s_log[tl][j];
            if (v > b2) { b2 = v; i2 = j; }
        }
        float z  = expf(b2 - b1);
        float s  = 1.0f + z;
        float w1 = 1.0f / s;
        float w2 = z / s;

        int p1 = atomicAdd(&g_count[i1], 1);
        g_tok[i1 * N_TOK + p1] = t;  g_wt[i1 * N_TOK + p1] = w1;
        int p2 = atomicAdd(&g_count[i2], 1);
        g_tok[i2 * N_TOK + p2] = t;  g_wt[i2 * N_TOK + p2] = w2;
        g_assign[t] = make_int4(i1, p1, i2, p2);
    }
}

__global__ void scan_kernel() {
    if (threadIdx.x == 0) {
        int s = 0;
        for (int e = 0; e < NE; e++) { g_base[e] = s; s += g_count[e]; }
    }
}

// ---------------------------------------------------------------------------
// Grouped GEMM: warp-level bf16 HMMA (mma.sync), 3-pass split precision.
// CTA 128x128, 8 warps (4m x 2n), warp tile 32x64.
// ---------------------------------------------------------------------------
__global__ __launch_bounds__(256, 2) void moe_gemm_kernel(
    const float* __restrict__ x,
    const float* __restrict__ ew,
    const float* __restrict__ eb)
{
    int e   = blockIdx.z;
    int cnt = g_count[e];
    int m0  = blockIdx.y * BM;
    if (m0 >= cnt) return;
    int n0  = blockIdx.x * BN;

    extern __shared__ char dyn[];
    __shared__ int   s_tok[BM];
    __shared__ float s_w[BM];

    int tid = threadIdx.x, wid = tid >> 5, lane = tid & 31;

    uint32_t dynu = smem_u32(dyn);
    uint32_t pad  = (1024u - (dynu & 1023u)) & 1023u;
    char* tb = dyn + pad;
    uint32_t tbu = dynu + pad;
    char* Ah = tb;           uint32_t Ahu = tbu;            // [128m][64k] bf16, 128B rows
    char* Al = tb + 16384;   uint32_t Alu = tbu + 16384;
    char* Bh = tb + 32768;   uint32_t Bhu = tbu + 32768;    // 2 halves: [64k][64n] bf16
    char* Bl = tb + 49152;   uint32_t Blu = tbu + 49152;

    if (tid < BM) {
        int gm = m0 + tid;
        if (gm < cnt) { s_tok[tid] = g_tok[e * N_TOK + gm]; s_w[tid] = g_wt[e * N_TOK + gm]; }
        else          { s_tok[tid] = -1;                    s_w[tid] = 0.0f; }
    }
    __syncthreads();

    // gmem->smem loader mappings
    int am  = tid >> 1;                 // A row 0..127
    int akb = (tid & 1) * 32;           // k half
    int atk = s_tok[am];
    const float* arow = x + (size_t)(atk < 0 ? 0 : atk) * D_IN;
    int bk  = tid >> 2;                 // B k row 0..63
    int bnb = (tid & 3) * 4;
    const float* wrow = ew + (size_t)e * D_IN * D_OUT + (size_t)bk * D_OUT + n0;

    int warp_m = wid >> 1;              // 0..3 -> rows 32*warp_m
    int warp_n = wid & 1;               // 0..1 -> cols 64*warp_n (selects B half)
    uint32_t BhW = Bhu + warp_n * 8192;
    uint32_t BlW = Blu + warp_n * 8192;

    // ldmatrix lane address components
    int l15 = lane & 15;
    int lhi = (lane >> 4) & 1;

    float acc[2][8][4];
    #pragma unroll
    for (int tm = 0; tm < 2; tm++)
        #pragma unroll
        for (int nt = 0; nt < 8; nt++)
            #pragma unroll
            for (int q = 0; q < 4; q++) acc[tm][nt][q] = 0.0f;

    for (int k0 = 0; k0 < D_IN; k0 += BKC) {
        // ---- stage A (gathered tokens) ----
        #pragma unroll
        for (int i = 0; i < 8; i++) {
            int kl = akb + i * 4;
            float4 v = (atk >= 0) ? *(const float4*)(arow + k0 + kl)
                                  : make_float4(0.f, 0.f, 0.f, 0.f);
            store_hl(Ah, Al, (uint32_t)(am * 128 + kl * 2), v);
        }
        // ---- stage B ----
        #pragma unroll
        for (int i = 0; i < 8; i++) {
            int n = bnb + i * 16;
            float4 v = *(const float4*)(wrow + (size_t)k0 * D_OUT + n);
            int h = n >> 6, nl = n & 63;
            store_hl(Bh + h * 8192, Bl + h * 8192, (uint32_t)(bk * 128 + nl * 2), v);
        }
        __syncthreads();

        // ---- compute: 4 k16 steps ----
        #pragma unroll
        for (int ks = 0; ks < 4; ks++) {
            uint32_t ah[2][4], al[2][4];
            #pragma unroll
            for (int tm = 0; tm < 2; tm++) {
                uint32_t offA = (uint32_t)((warp_m * 32 + tm * 16 + l15) * 128
                                           + (ks * 16 + lhi * 8) * 2);
                uint32_t sa = swz(offA);
                ldsm_x4(ah[tm], Ahu + sa);
                ldsm_x4(al[tm], Alu + sa);
            }
            #pragma unroll
            for (int g = 0; g < 4; g++) {
                uint32_t offB = (uint32_t)((ks * 16 + l15) * 128
                                           + (g * 16 + lhi * 8) * 2);
                uint32_t sb = swz(offB);
                uint32_t bh[4], bl[4];
                ldsm_x4t(bh, BhW + sb);
                ldsm_x4t(bl, BlW + sb);
                #pragma unroll
                for (int tm = 0; tm < 2; tm++) {
                    #pragma unroll
                    for (int sub = 0; sub < 2; sub++) {
                        float* c = acc[tm][g * 2 + sub];
                        mma_bf16(c, ah[tm], bh + sub * 2);
                        mma_bf16(c, ah[tm], bl + sub * 2);
                        mma_bf16(c, al[tm], bh + sub * 2);
                    }
                }
            }
        }
        __syncthreads();
    }

    // ---- epilogue: weighted + biased -> scratch (no atomics) ----
    int gq  = lane >> 2;        // 0..7
    int tig = lane & 3;         // 0..3
    int colb = n0 + warp_n * 64;
    const float* bias = eb + (size_t)e * D_OUT + colb;

    #pragma unroll
    for (int tm = 0; tm < 2; tm++) {
        int r_lo = warp_m * 32 + tm * 16 + gq;
        int r_hi = r_lo + 8;
        int tk1 = s_tok[r_lo], tk2 = s_tok[r_hi];
        float w1 = s_w[r_lo],  w2 = s_w[r_hi];
        float* o1 = g_scratch + (size_t)(g_base[e] + m0 + r_lo) * D_OUT + colb;
        float* o2 = g_scratch + (size_t)(g_base[e] + m0 + r_hi) * D_OUT + colb;
        #pragma unroll
        for (int nt = 0; nt < 8; nt++) {
            int c = nt * 8 + tig * 2;
            float b0 = bias[c], b1 = bias[c + 1];
            if (tk1 >= 0) {
                float2 v;
                v.x = w1 * (acc[tm][nt][0] + b0);
                v.y = w1 * (acc[tm][nt][1] + b1);
                *(float2*)(o1 + c) = v;
            }
            if (tk2 >= 0) {
                float2 v;
                v.x = w2 * (acc[tm][nt][2] + b0);
                v.y = w2 * (acc[tm][nt][3] + b1);
                *(float2*)(o2 + c) = v;
            }
        }
    }
}

// ---------------------------------------------------------------------------
// Combine: out[t] = scratch[slot(e1,p1)] + scratch[slot(e2,p2)]
// ---------------------------------------------------------------------------
__global__ __launch_bounds__(128) void combine_kernel(float* __restrict__ out)
{
    int t = blockIdx.x;
    int c = threadIdx.x * 4;
    int4 a = g_assign[t];
    int r1 = g_base[a.x] + a.y;
    int r2 = g_base[a.z] + a.w;
    float4 v1 = *(const float4*)(g_scratch + (size_t)r1 * D_OUT + c);
    float4 v2 = *(const float4*)(g_scratch + (size_t)r2 * D_OUT + c);
    float4 o;
    o.x = v1.x + v2.x; o.y = v1.y + v2.y; o.z = v1.z + v2.z; o.w = v1.w + v2.w;
    *(float4*)(out + (size_t)t * D_OUT + c) = o;
}

// ---------------------------------------------------------------------------
extern "C" void kernel_launch(void* const* d_in, const int* in_sizes, int n_in,
                              void* d_out, int out_size)
{
    const float* x  = (const float*)d_in[0];
    const float* gw = (const float*)d_in[1];
    const float* gb = (const float*)d_in[2];
    const float* ew = (const float*)d_in[3];
    const float* eb = (const float*)d_in[4];
    float* out = (float*)d_out;

    void* cptr = nullptr;
    cudaGetSymbolAddress(&cptr, g_count);
    cudaMemsetAsync(cptr, 0, NE * sizeof(int));

    router_kernel<<<N_TOK / 16, 256>>>(x, gw, gb);
    scan_kernel<<<1, 32>>>();

    cudaFuncSetAttribute(moe_gemm_kernel,
                         cudaFuncAttributeMaxDynamicSharedMemorySize, SMEM_DYN);
    dim3 grid(D_OUT / BN, N_TOK / BM, NE);
    moe_gemm_kernel<<<grid, 256, SMEM_DYN>>>(x, ew, eb);

    combine_kernel<<<N_TOK, 128>>>(out);
}